// round 9
// baseline (speedup 1.0000x reference)
#include <cuda_runtime.h>
#include <cuda_bf16.h>
#include <stdint.h>
#include <math.h>

#define B_ 4
#define T_ 4096
#define C_ 1024
#define HD 64
#define PAD 68

// fp32 scratch (no cudaMalloc allowed)
__device__ float g_q[B_ * T_ * HD];
__device__ float g_k[B_ * T_ * HD];
__device__ float g_v[B_ * T_ * HD];
__device__ float g_vt[B_ * HD * T_];   // V transposed: [b][h][t]

// ---------------------------------------------------------------------------
// helpers
// ---------------------------------------------------------------------------
__device__ __forceinline__ uint32_t smem_u32(const void* p) {
    uint32_t a;
    asm("{ .reg .u64 t; cvta.to.shared.u64 t, %1; cvt.u32.u64 %0, t; }"
        : "=r"(a) : "l"(p));
    return a;
}
__device__ __forceinline__ void mma16816(float* c, const uint32_t* a,
                                         uint32_t b0, uint32_t b1) {
    asm volatile(
        "mma.sync.aligned.m16n8k16.row.col.f32.bf16.bf16.f32 "
        "{%0,%1,%2,%3}, {%4,%5,%6,%7}, {%8,%9}, {%0,%1,%2,%3};"
        : "+f"(c[0]), "+f"(c[1]), "+f"(c[2]), "+f"(c[3])
        : "r"(a[0]), "r"(a[1]), "r"(a[2]), "r"(a[3]), "r"(b0), "r"(b1));
}
__device__ __forceinline__ void ldmx4(uint32_t& r0, uint32_t& r1,
                                      uint32_t& r2, uint32_t& r3, uint32_t addr) {
    asm volatile("ldmatrix.sync.aligned.m8n8.x4.shared.b16 {%0,%1,%2,%3}, [%4];"
                 : "=r"(r0), "=r"(r1), "=r"(r2), "=r"(r3) : "r"(addr));
}
__device__ __forceinline__ uint32_t pk_bf16(float lo, float hi) {
    __nv_bfloat162 h = __floats2bfloat162_rn(lo, hi);
    return *(uint32_t*)&h;
}

// ===========================================================================
// Kernel 1: fused QKV projection (fp32 SIMT — proven 92us)
// ===========================================================================
#define KC 32
__global__ __launch_bounds__(256) void qkv_kernel(
    const float* __restrict__ x, const float* __restrict__ Wq,
    const float* __restrict__ Wk, const float* __restrict__ Wv)
{
    __shared__ float Xt[KC][PAD];
    __shared__ float Wqs[KC][PAD];
    __shared__ float Wks[KC][PAD];
    __shared__ float Wvs[KC][PAD];

    const int tid = threadIdx.x;
    const int ty = tid >> 4;
    const int tx = tid & 15;
    const long row0 = (long)blockIdx.x * 64;

    float aq[4][4] = {}, ak[4][4] = {}, av[4][4] = {};

    for (int k0 = 0; k0 < C_; k0 += KC) {
        __syncthreads();
        for (int f = tid; f < 64 * KC / 4; f += 256) {
            int r = f >> 3;
            int kq = (f & 7) * 4;
            float4 xv = *(const float4*)(x + (row0 + r) * C_ + k0 + kq);
            Xt[kq + 0][r] = xv.x; Xt[kq + 1][r] = xv.y;
            Xt[kq + 2][r] = xv.z; Xt[kq + 3][r] = xv.w;
        }
        for (int f = tid; f < KC * 64 / 4; f += 256) {
            int kk = f >> 4;
            int c4 = (f & 15) * 4;
            *(float4*)&Wqs[kk][c4] = *(const float4*)(Wq + (long)(k0 + kk) * HD + c4);
            *(float4*)&Wks[kk][c4] = *(const float4*)(Wk + (long)(k0 + kk) * HD + c4);
            *(float4*)&Wvs[kk][c4] = *(const float4*)(Wv + (long)(k0 + kk) * HD + c4);
        }
        __syncthreads();

        #pragma unroll 8
        for (int kk = 0; kk < KC; kk++) {
            float4 a4 = *(float4*)&Xt[kk][ty * 4];
            float4 q4 = *(float4*)&Wqs[kk][tx * 4];
            float4 k4 = *(float4*)&Wks[kk][tx * 4];
            float4 v4 = *(float4*)&Wvs[kk][tx * 4];
            float a[4] = {a4.x, a4.y, a4.z, a4.w};
            float bq[4] = {q4.x, q4.y, q4.z, q4.w};
            float bk[4] = {k4.x, k4.y, k4.z, k4.w};
            float bv[4] = {v4.x, v4.y, v4.z, v4.w};
            #pragma unroll
            for (int i = 0; i < 4; i++)
                #pragma unroll
                for (int j = 0; j < 4; j++) {
                    aq[i][j] = fmaf(a[i], bq[j], aq[i][j]);
                    ak[i][j] = fmaf(a[i], bk[j], ak[i][j]);
                    av[i][j] = fmaf(a[i], bv[j], av[i][j]);
                }
        }
    }

    #pragma unroll
    for (int i = 0; i < 4; i++) {
        long r = row0 + ty * 4 + i;
        *(float4*)(g_q + r * HD + tx * 4) = make_float4(aq[i][0], aq[i][1], aq[i][2], aq[i][3]);
        *(float4*)(g_k + r * HD + tx * 4) = make_float4(ak[i][0], ak[i][1], ak[i][2], ak[i][3]);
        *(float4*)(g_v + r * HD + tx * 4) = make_float4(av[i][0], av[i][1], av[i][2], av[i][3]);
    }
}

// ===========================================================================
// Kernel 1b: transpose V -> g_vt[b][h][t]
// Stride 68 floats = 272 B (16-aligned) — float4 stores legal on every row.
// ===========================================================================
__global__ __launch_bounds__(256) void vt_kernel()
{
    __shared__ float s[64][68];
    const int tid = threadIdx.x;
    const long t0 = (long)blockIdx.x * 64;
    const int b = blockIdx.y;

    // read 64 tokens x 64 h, coalesced
    {
        int r = tid >> 2, c0 = (tid & 3) * 16;
        const float* vb = g_v + ((size_t)b * T_ + t0 + r) * HD + c0;
        #pragma unroll
        for (int i = 0; i < 4; i++)
            *(float4*)&s[r][c0 + i * 4] = *(const float4*)(vb + i * 4);
    }
    __syncthreads();
    // write transposed rows, coalesced
    {
        int h = tid >> 2, ts = (tid & 3) * 16;
        float* d = g_vt + ((size_t)b * HD + h) * T_ + t0 + ts;
        #pragma unroll
        for (int i = 0; i < 16; i += 4)
            *(float4*)(d + i) = make_float4(s[ts + i][h], s[ts + i + 1][h],
                                            s[ts + i + 2][h], s[ts + i + 3][h]);
    }
}

// ===========================================================================
// Kernel 2: mma.sync bf16 flash attention (causal). BM=64, BN=64, paired
// q-tiles (63-p, p) -> 65 iters/block. Warp w: rows (w&3)*16, key half w>>2.
// ldmatrix.x4 fragment loads; V pre-transposed; PV = Phi*Vhi+Plo*Vhi+Phi*Vlo.
// ===========================================================================
#define LDW 72
#define ORED_LD 68

__global__ __launch_bounds__(256, 1) void attn_mma(float* __restrict__ out)
{
    __shared__ __align__(16) __nv_bfloat16 QS[64 * LDW];
    __shared__ __align__(16) __nv_bfloat16 KS[64 * LDW];
    __shared__ __align__(16) __nv_bfloat16 VH[64 * LDW];
    __shared__ __align__(16) __nv_bfloat16 VL[64 * LDW];

    // epilogue overlay on KS..VL (only used between syncthreads)
    float* Ored = (float*)KS;                    // [64][68] f32
    float* lred = Ored + 64 * ORED_LD;           // [64] (spills into VH region)

    const int tid = threadIdx.x;
    const int w = tid >> 5;
    const int lane = tid & 31;
    const int g = lane >> 2;
    const int t = lane & 3;
    const int m0 = (w & 3) * 16;
    const int kh = w >> 2;
    const int p = blockIdx.x;
    const int b = blockIdx.y;
    const float scale = 0.03125f;

    const uint32_t qsb = smem_u32(QS);
    const uint32_t ksb = smem_u32(KS);
    const uint32_t vhb = smem_u32(VH);
    const uint32_t vlb = smem_u32(VL);

    // per-lane ldmatrix row constants (element offsets)
    const int lr = lane & 7;             // row within 8x8 matrix
    const int lh = (lane >> 3) & 1;      // column half (0/8)
    const int lj = lane >> 4;            // tile pair offset (0/1)
    const uint32_t q_lane  = (uint32_t)((m0 + lh * 8 + lr) * LDW + lj * 8);
    const uint32_t qk_lane = (uint32_t)((kh * 32 + lj * 8 + lr) * LDW + lh * 8);
    const uint32_t pv_lane = (uint32_t)((lj * 8 + lr) * LDW + kh * 32 + lh * 8);

    for (int half = 0; half < 2; half++) {
        const int it = (half == 0) ? (63 - p) : p;
        const int njt = it + 1;
        const int qrow0 = it * 64 + m0 + g;
        const int qrow8 = qrow0 + 8;

        // ---- Stage Q tile (fp32 -> bf16 smem) ----
        {
            const float* qb = g_q + ((size_t)b * T_ + (size_t)it * 64) * HD;
            int r = tid >> 2, c0 = (tid & 3) * 16;
            #pragma unroll
            for (int i = 0; i < 4; i++) {
                float4 v4 = *(const float4*)(qb + r * HD + c0 + i * 4);
                *(uint32_t*)&QS[r * LDW + c0 + i * 4]     = pk_bf16(v4.x, v4.y);
                *(uint32_t*)&QS[r * LDW + c0 + i * 4 + 2] = pk_bf16(v4.z, v4.w);
            }
        }
        __syncthreads();

        uint32_t aQ[4][4];
        #pragma unroll
        for (int ks = 0; ks < 4; ks++)
            ldmx4(aQ[ks][0], aQ[ks][1], aQ[ks][2], aQ[ks][3],
                  qsb + 2 * (q_lane + ks * 16));

        float O[8][4];
        #pragma unroll
        for (int j = 0; j < 8; j++)
            #pragma unroll
            for (int i = 0; i < 4; i++) O[j][i] = 0.0f;
        float l_g = 0.0f, l_g8 = 0.0f;

        for (int jt = 0; jt < njt; jt++) {
            __syncthreads();
            // ---- Stage K tile + VH/VL from pre-transposed V (vectorized) ----
            {
                int r = tid >> 2, c0 = (tid & 3) * 16;
                const float* kb = g_k + ((size_t)b * T_ + (size_t)jt * 64 + r) * HD + c0;
                #pragma unroll
                for (int i = 0; i < 4; i++) {
                    float4 kv = *(const float4*)(kb + i * 4);
                    *(uint32_t*)&KS[r * LDW + c0 + i * 4]     = pk_bf16(kv.x, kv.y);
                    *(uint32_t*)&KS[r * LDW + c0 + i * 4 + 2] = pk_bf16(kv.z, kv.w);
                }
                // VH/VL: thread owns h-row r over 16 keys c0..c0+15
                const float* vt = g_vt + ((size_t)b * HD + r) * T_ + (size_t)jt * 64 + c0;
                #pragma unroll
                for (int i = 0; i < 4; i++) {
                    float4 vv = *(const float4*)(vt + i * 4);
                    __nv_bfloat16 h0 = __float2bfloat16(vv.x);
                    __nv_bfloat16 h1 = __float2bfloat16(vv.y);
                    __nv_bfloat16 h2 = __float2bfloat16(vv.z);
                    __nv_bfloat16 h3 = __float2bfloat16(vv.w);
                    __nv_bfloat162 hA = __halves2bfloat162(h0, h1);
                    __nv_bfloat162 hB = __halves2bfloat162(h2, h3);
                    *(uint32_t*)&VH[r * LDW + c0 + i * 4]     = *(uint32_t*)&hA;
                    *(uint32_t*)&VH[r * LDW + c0 + i * 4 + 2] = *(uint32_t*)&hB;
                    *(uint32_t*)&VL[r * LDW + c0 + i * 4] = pk_bf16(
                        vv.x - __bfloat162float(h0), vv.y - __bfloat162float(h1));
                    *(uint32_t*)&VL[r * LDW + c0 + i * 4 + 2] = pk_bf16(
                        vv.z - __bfloat162float(h2), vv.w - __bfloat162float(h3));
                }
            }
            __syncthreads();

            // ---- S = Q K^T over this warp's 32-key half (ldmatrix b-frags) ----
            float S[4][4];
            #pragma unroll
            for (int j = 0; j < 4; j++)
                #pragma unroll
                for (int i = 0; i < 4; i++) S[j][i] = 0.0f;
            #pragma unroll
            for (int ks = 0; ks < 4; ks++) {
                #pragma unroll
                for (int j0 = 0; j0 < 4; j0 += 2) {
                    uint32_t b0, b1, b2, b3;
                    ldmx4(b0, b1, b2, b3,
                          ksb + 2 * (qk_lane + (uint32_t)(j0 * 8 * LDW + ks * 16)));
                    mma16816(S[j0], aQ[ks], b0, b1);
                    mma16816(S[j0 + 1], aQ[ks], b2, b3);
                }
            }

            // ---- softmax (bounded logits, no max subtraction) ----
            const int kb0 = jt * 64 + kh * 32;
            const bool dm = (kb0 + 31) > qrow0;
            #pragma unroll
            for (int j = 0; j < 4; j++) {
                int k0 = kb0 + 8 * j + 2 * t;
                float p0 = __expf(S[j][0] * scale);
                float p1 = __expf(S[j][1] * scale);
                float p2 = __expf(S[j][2] * scale);
                float p3 = __expf(S[j][3] * scale);
                if (dm) {
                    if (k0 > qrow0)     p0 = 0.0f;
                    if (k0 + 1 > qrow0) p1 = 0.0f;
                    if (k0 > qrow8)     p2 = 0.0f;
                    if (k0 + 1 > qrow8) p3 = 0.0f;
                }
                S[j][0] = p0; S[j][1] = p1; S[j][2] = p2; S[j][3] = p3;
                l_g  += p0 + p1;
                l_g8 += p2 + p3;
            }

            // ---- pack P hi/lo a-fragments ----
            uint32_t aH[2][4], aL[2][4];
            #pragma unroll
            for (int kp = 0; kp < 2; kp++)
                #pragma unroll
                for (int hf = 0; hf < 2; hf++) {
                    float* sp = S[2 * kp + hf];
                    #pragma unroll
                    for (int rr = 0; rr < 2; rr++) {
                        float p0 = sp[2 * rr], p1 = sp[2 * rr + 1];
                        __nv_bfloat16 h0 = __float2bfloat16(p0);
                        __nv_bfloat16 h1 = __float2bfloat16(p1);
                        __nv_bfloat162 hh = __halves2bfloat162(h0, h1);
                        aH[kp][hf * 2 + rr] = *(uint32_t*)&hh;
                        aL[kp][hf * 2 + rr] = pk_bf16(
                            p0 - __bfloat162float(h0), p1 - __bfloat162float(h1));
                    }
                }

            // ---- O += Phi Vhi + Plo Vhi + Phi Vlo (ldmatrix b-frags) ----
            #pragma unroll
            for (int ks = 0; ks < 2; ks++) {
                #pragma unroll
                for (int j0 = 0; j0 < 8; j0 += 2) {
                    uint32_t off = 2 * (pv_lane + (uint32_t)(j0 * 8 * LDW + ks * 16));
                    uint32_t h0, h1, h2, h3, l0, l1, l2, l3;
                    ldmx4(h0, h1, h2, h3, vhb + off);
                    ldmx4(l0, l1, l2, l3, vlb + off);
                    mma16816(O[j0], aH[ks], h0, h1);
                    mma16816(O[j0], aL[ks], h0, h1);
                    mma16816(O[j0], aH[ks], l0, l1);
                    mma16816(O[j0 + 1], aH[ks], h2, h3);
                    mma16816(O[j0 + 1], aL[ks], h2, h3);
                    mma16816(O[j0 + 1], aH[ks], l2, l3);
                }
            }
        }

        // ---- reduce l across quad ----
        l_g  += __shfl_xor_sync(0xffffffffu, l_g, 1);
        l_g  += __shfl_xor_sync(0xffffffffu, l_g, 2);
        l_g8 += __shfl_xor_sync(0xffffffffu, l_g8, 1);
        l_g8 += __shfl_xor_sync(0xffffffffu, l_g8, 2);

        __syncthreads();   // all PV smem reads done before Ored overlay

        if (kh == 1) {
            #pragma unroll
            for (int j = 0; j < 8; j++) {
                int col = 8 * j + 2 * t;
                *(float2*)&Ored[(m0 + g) * ORED_LD + col] = make_float2(O[j][0], O[j][1]);
                *(float2*)&Ored[(m0 + g + 8) * ORED_LD + col] = make_float2(O[j][2], O[j][3]);
            }
            if (t == 0) { lred[m0 + g] = l_g; lred[m0 + g + 8] = l_g8; }
        }
        __syncthreads();

        if (kh == 0) {
            const float il0 = 1.0f / (l_g + lred[m0 + g]);
            const float il1 = 1.0f / (l_g8 + lred[m0 + g + 8]);
            float* ob = out + ((size_t)b * T_ + (size_t)it * 64 + m0) * HD;
            #pragma unroll
            for (int j = 0; j < 8; j++) {
                int col = 8 * j + 2 * t;
                float2 p0 = *(float2*)&Ored[(m0 + g) * ORED_LD + col];
                float2 p1 = *(float2*)&Ored[(m0 + g + 8) * ORED_LD + col];
                *(float2*)&ob[g * HD + col] =
                    make_float2((O[j][0] + p0.x) * il0, (O[j][1] + p0.y) * il0);
                *(float2*)&ob[(g + 8) * HD + col] =
                    make_float2((O[j][2] + p1.x) * il1, (O[j][3] + p1.y) * il1);
            }
        }
        __syncthreads();   // Ored/lred reads done before next half re-stages
    }
}

// ===========================================================================
extern "C" void kernel_launch(void* const* d_in, const int* in_sizes, int n_in,
                              void* d_out, int out_size)
{
    const float* x  = (const float*)d_in[0];
    const float* Wq = (const float*)d_in[1];
    const float* Wk = (const float*)d_in[2];
    const float* Wv = (const float*)d_in[3];
    float* out = (float*)d_out;

    qkv_kernel<<<(B_ * T_) / 64, 256>>>(x, Wq, Wk, Wv);
    vt_kernel<<<dim3(T_ / 64, B_), 256>>>();
    attn_mma<<<dim3(32, B_), 256>>>(out);
}

// round 10
// speedup vs baseline: 1.4819x; 1.4819x over previous
#include <cuda_runtime.h>
#include <cuda_bf16.h>
#include <stdint.h>
#include <math.h>

#define B_ 4
#define T_ 4096
#define C_ 1024
#define HD 64

// scratch (no cudaMalloc allowed)
__device__ __nv_bfloat16 g_qh[B_ * T_ * HD];        // Q bf16 [b*t][h]
__device__ __nv_bfloat16 g_kh[B_ * T_ * HD];        // K bf16 [b*t][h]
__device__ float         g_v [B_ * T_ * HD];        // V fp32 [b*t][h]
__device__ __nv_bfloat16 g_vth[B_ * HD * T_];       // V^T hi bf16 [b][h][t]
__device__ __nv_bfloat16 g_vtl[B_ * HD * T_];       // V^T lo
__device__ __nv_bfloat16 g_wth[3 * HD * C_];        // W^T hi bf16 [m][n][k]
__device__ __nv_bfloat16 g_wvl[HD * C_];            // Wv^T lo

// ---------------------------------------------------------------------------
// helpers
// ---------------------------------------------------------------------------
__device__ __forceinline__ uint32_t smem_u32(const void* p) {
    uint32_t a;
    asm("{ .reg .u64 t; cvta.to.shared.u64 t, %1; cvt.u32.u64 %0, t; }"
        : "=r"(a) : "l"(p));
    return a;
}
__device__ __forceinline__ void mma16816(float* c, const uint32_t* a,
                                         uint32_t b0, uint32_t b1) {
    asm volatile(
        "mma.sync.aligned.m16n8k16.row.col.f32.bf16.bf16.f32 "
        "{%0,%1,%2,%3}, {%4,%5,%6,%7}, {%8,%9}, {%0,%1,%2,%3};"
        : "+f"(c[0]), "+f"(c[1]), "+f"(c[2]), "+f"(c[3])
        : "r"(a[0]), "r"(a[1]), "r"(a[2]), "r"(a[3]), "r"(b0), "r"(b1));
}
__device__ __forceinline__ void ldmx4(uint32_t& r0, uint32_t& r1,
                                      uint32_t& r2, uint32_t& r3, uint32_t addr) {
    asm volatile("ldmatrix.sync.aligned.m8n8.x4.shared.b16 {%0,%1,%2,%3}, [%4];"
                 : "=r"(r0), "=r"(r1), "=r"(r2), "=r"(r3) : "r"(addr));
}
__device__ __forceinline__ uint32_t pk_bf16(float lo, float hi) {
    __nv_bfloat162 h = __floats2bfloat162_rn(lo, hi);
    return *(uint32_t*)&h;
}

// ===========================================================================
// Kernel 0: transpose + bf16-split W -> g_wth [m][n][k], g_wvl (v only)
// grid (16, 3): 64-k-row tile per block.
// ===========================================================================
__global__ __launch_bounds__(256) void prep_w(
    const float* __restrict__ Wq, const float* __restrict__ Wk,
    const float* __restrict__ Wv)
{
    __shared__ float s[64][68];
    const int tid = threadIdx.x;
    const int kc = blockIdx.x;          // k-chunk of 64
    const int m = blockIdx.y;           // 0=q 1=k 2=v
    const float* W = (m == 0) ? Wq : (m == 1) ? Wk : Wv;

    {   // read [64 k][64 n] coalesced
        int r = tid >> 2, c0 = (tid & 3) * 16;
        const float* wp = W + ((size_t)(kc * 64) + r) * HD + c0;
        #pragma unroll
        for (int i = 0; i < 4; i++)
            *(float4*)&s[r][c0 + i * 4] = *(const float4*)(wp + i * 4);
    }
    __syncthreads();
    {   // write W^T rows (n-major), hi (+ lo for v)
        int n = tid >> 2, k0 = (tid & 3) * 16;
        __nv_bfloat16* dh = g_wth + ((size_t)m * HD + n) * C_ + kc * 64 + k0;
        __nv_bfloat16* dl = g_wvl + (size_t)n * C_ + kc * 64 + k0;
        #pragma unroll
        for (int i = 0; i < 8; i++) {
            float f0 = s[k0 + 2 * i][n], f1 = s[k0 + 2 * i + 1][n];
            __nv_bfloat16 h0 = __float2bfloat16(f0);
            __nv_bfloat16 h1 = __float2bfloat16(f1);
            __nv_bfloat162 hh = __halves2bfloat162(h0, h1);
            *(uint32_t*)(dh + 2 * i) = *(uint32_t*)&hh;
            if (m == 2)
                *(uint32_t*)(dl + 2 * i) = pk_bf16(
                    f0 - __bfloat162float(h0), f1 - __bfloat162float(h1));
        }
    }
}

// ===========================================================================
// Kernel 1: QKV projection on bf16 mma.sync. BM=128 rows, 8 warps (16 rows
// each, all 192 output cols). q,k single-pass bf16; v 3-pass hi/lo.
// ===========================================================================
#define KQ 32     // k-chunk
#define XS 40     // X smem stride (bf16): 80B = 5x16, conflict-free
#define WS 40

__global__ __launch_bounds__(256) void qkv_tc(const float* __restrict__ x)
{
    __shared__ __align__(16) __nv_bfloat16 XH[128 * XS];
    __shared__ __align__(16) __nv_bfloat16 XL[128 * XS];
    __shared__ __align__(16) __nv_bfloat16 WT[4][64 * WS];  // qh, kh, vh, vl

    const int tid = threadIdx.x;
    const int w = tid >> 5;
    const int lane = tid & 31;
    const int g = lane >> 2;
    const int t = lane & 3;
    const int m0 = w * 16;
    const long row0 = (long)blockIdx.x * 128;

    const int lr = lane & 7, lh = (lane >> 3) & 1, lj = lane >> 4;
    const uint32_t a_lane = (uint32_t)((m0 + lh * 8 + lr) * XS + lj * 8);
    const uint32_t b_lane = (uint32_t)((lj * 8 + lr) * WS + lh * 8);
    const uint32_t xhb = smem_u32(XH), xlb = smem_u32(XL);
    const uint32_t wq = smem_u32(WT[0]), wk = smem_u32(WT[1]);
    const uint32_t wvh = smem_u32(WT[2]), wvl = smem_u32(WT[3]);

    float aq[8][4], ak[8][4], av[8][4];
    #pragma unroll
    for (int j = 0; j < 8; j++)
        #pragma unroll
        for (int i = 0; i < 4; i++) { aq[j][i] = 0; ak[j][i] = 0; av[j][i] = 0; }

    for (int k0 = 0; k0 < C_; k0 += KQ) {
        __syncthreads();
        // stage X chunk fp32 -> XH/XL
        {
            int r = tid >> 1, c0 = (tid & 1) * 16;
            const float* xp = x + (row0 + r) * C_ + k0 + c0;
            #pragma unroll
            for (int i = 0; i < 4; i++) {
                float4 v = *(const float4*)(xp + i * 4);
                __nv_bfloat16 h0 = __float2bfloat16(v.x);
                __nv_bfloat16 h1 = __float2bfloat16(v.y);
                __nv_bfloat16 h2 = __float2bfloat16(v.z);
                __nv_bfloat16 h3 = __float2bfloat16(v.w);
                __nv_bfloat162 a01 = __halves2bfloat162(h0, h1);
                __nv_bfloat162 a23 = __halves2bfloat162(h2, h3);
                *(uint32_t*)&XH[r * XS + c0 + i * 4]     = *(uint32_t*)&a01;
                *(uint32_t*)&XH[r * XS + c0 + i * 4 + 2] = *(uint32_t*)&a23;
                *(uint32_t*)&XL[r * XS + c0 + i * 4] = pk_bf16(
                    v.x - __bfloat162float(h0), v.y - __bfloat162float(h1));
                *(uint32_t*)&XL[r * XS + c0 + i * 4 + 2] = pk_bf16(
                    v.z - __bfloat162float(h2), v.w - __bfloat162float(h3));
            }
        }
        // stage W chunks: 4 arrays x 64 rows x 32 bf16 (int4 copies)
        for (int f = tid; f < 1024; f += 256) {
            int arr = f >> 8, rw = (f >> 2) & 63, sg = f & 3;
            const __nv_bfloat16* src =
                (arr < 3) ? g_wth + ((size_t)arr * HD + rw) * C_ + k0 + sg * 8
                          : g_wvl + (size_t)rw * C_ + k0 + sg * 8;
            *(int4*)&WT[arr][rw * WS + sg * 8] = *(const int4*)src;
        }
        __syncthreads();

        uint32_t aH[2][4], aL[2][4];
        #pragma unroll
        for (int ks = 0; ks < 2; ks++) {
            ldmx4(aH[ks][0], aH[ks][1], aH[ks][2], aH[ks][3],
                  xhb + 2 * (a_lane + ks * 16));
            ldmx4(aL[ks][0], aL[ks][1], aL[ks][2], aL[ks][3],
                  xlb + 2 * (a_lane + ks * 16));
        }

        #pragma unroll
        for (int ks = 0; ks < 2; ks++) {
            #pragma unroll
            for (int j0 = 0; j0 < 8; j0 += 2) {
                uint32_t off = 2 * (b_lane + (uint32_t)(j0 * 8 * WS + ks * 16));
                uint32_t b0, b1, b2, b3;
                ldmx4(b0, b1, b2, b3, wq + off);
                mma16816(aq[j0], aH[ks], b0, b1);
                mma16816(aq[j0 + 1], aH[ks], b2, b3);
                ldmx4(b0, b1, b2, b3, wk + off);
                mma16816(ak[j0], aH[ks], b0, b1);
                mma16816(ak[j0 + 1], aH[ks], b2, b3);
                ldmx4(b0, b1, b2, b3, wvh + off);
                mma16816(av[j0], aH[ks], b0, b1);
                mma16816(av[j0], aL[ks], b0, b1);
                mma16816(av[j0 + 1], aH[ks], b2, b3);
                mma16816(av[j0 + 1], aL[ks], b2, b3);
                ldmx4(b0, b1, b2, b3, wvl + off);
                mma16816(av[j0], aH[ks], b0, b1);
                mma16816(av[j0 + 1], aH[ks], b2, b3);
            }
        }
    }

    // epilogue: q,k -> bf16; v -> fp32
    #pragma unroll
    for (int j = 0; j < 8; j++) {
        int col = 8 * j + 2 * t;
        size_t r0 = (size_t)(row0 + m0 + g) * HD + col;
        size_t r8 = (size_t)(row0 + m0 + g + 8) * HD + col;
        *(uint32_t*)&g_qh[r0] = pk_bf16(aq[j][0], aq[j][1]);
        *(uint32_t*)&g_qh[r8] = pk_bf16(aq[j][2], aq[j][3]);
        *(uint32_t*)&g_kh[r0] = pk_bf16(ak[j][0], ak[j][1]);
        *(uint32_t*)&g_kh[r8] = pk_bf16(ak[j][2], ak[j][3]);
        *(float2*)&g_v[r0] = make_float2(av[j][0], av[j][1]);
        *(float2*)&g_v[r8] = make_float2(av[j][2], av[j][3]);
    }
}

// ===========================================================================
// Kernel 1b: transpose + hi/lo split V -> g_vth/g_vtl [b][h][t]
// ===========================================================================
__global__ __launch_bounds__(256) void vt_kernel()
{
    __shared__ float s[64][68];
    const int tid = threadIdx.x;
    const long t0 = (long)blockIdx.x * 64;
    const int b = blockIdx.y;

    {
        int r = tid >> 2, c0 = (tid & 3) * 16;
        const float* vb = g_v + ((size_t)b * T_ + t0 + r) * HD + c0;
        #pragma unroll
        for (int i = 0; i < 4; i++)
            *(float4*)&s[r][c0 + i * 4] = *(const float4*)(vb + i * 4);
    }
    __syncthreads();
    {
        int h = tid >> 2, ts = (tid & 3) * 16;
        __nv_bfloat16* dh = g_vth + ((size_t)b * HD + h) * T_ + t0 + ts;
        __nv_bfloat16* dl = g_vtl + ((size_t)b * HD + h) * T_ + t0 + ts;
        #pragma unroll
        for (int i = 0; i < 8; i++) {
            float f0 = s[ts + 2 * i][h], f1 = s[ts + 2 * i + 1][h];
            __nv_bfloat16 h0 = __float2bfloat16(f0);
            __nv_bfloat16 h1 = __float2bfloat16(f1);
            __nv_bfloat162 hh = __halves2bfloat162(h0, h1);
            *(uint32_t*)(dh + 2 * i) = *(uint32_t*)&hh;
            *(uint32_t*)(dl + 2 * i) = pk_bf16(
                f0 - __bfloat162float(h0), f1 - __bfloat162float(h1));
        }
    }
}

// ===========================================================================
// Kernel 2: mma.sync bf16 flash attention (causal). BM=64, BN=64, paired
// q-tiles (63-p, p). Staging is now pure int4 copies from bf16 globals.
// ===========================================================================
#define LDW 72
#define ORED_LD 68

__global__ __launch_bounds__(256, 1) void attn_mma(float* __restrict__ out)
{
    __shared__ __align__(16) __nv_bfloat16 QS[64 * LDW];
    __shared__ __align__(16) __nv_bfloat16 KS[64 * LDW];
    __shared__ __align__(16) __nv_bfloat16 VH[64 * LDW];
    __shared__ __align__(16) __nv_bfloat16 VL[64 * LDW];

    float* Ored = (float*)KS;                    // [64][68] f32 overlay
    float* lred = Ored + 64 * ORED_LD;

    const int tid = threadIdx.x;
    const int w = tid >> 5;
    const int lane = tid & 31;
    const int g = lane >> 2;
    const int t = lane & 3;
    const int m0 = (w & 3) * 16;
    const int kh = w >> 2;
    const int p = blockIdx.x;
    const int b = blockIdx.y;
    const float scale = 0.03125f;

    const uint32_t qsb = smem_u32(QS);
    const uint32_t ksb = smem_u32(KS);
    const uint32_t vhb = smem_u32(VH);
    const uint32_t vlb = smem_u32(VL);

    const int lr = lane & 7;
    const int lh = (lane >> 3) & 1;
    const int lj = lane >> 4;
    const uint32_t q_lane  = (uint32_t)((m0 + lh * 8 + lr) * LDW + lj * 8);
    const uint32_t qk_lane = (uint32_t)((kh * 32 + lj * 8 + lr) * LDW + lh * 8);
    const uint32_t pv_lane = (uint32_t)((lj * 8 + lr) * LDW + kh * 32 + lh * 8);

    for (int half = 0; half < 2; half++) {
        const int it = (half == 0) ? (63 - p) : p;
        const int njt = it + 1;
        const int qrow0 = it * 64 + m0 + g;
        const int qrow8 = qrow0 + 8;

        // ---- Stage Q (int4 copies) ----
        {
            int r = tid >> 2, c0 = (tid & 3) * 16;
            const __nv_bfloat16* qb = g_qh + ((size_t)b * T_ + it * 64 + r) * HD + c0;
            *(int4*)&QS[r * LDW + c0]     = *(const int4*)qb;
            *(int4*)&QS[r * LDW + c0 + 8] = *(const int4*)(qb + 8);
        }
        __syncthreads();

        uint32_t aQ[4][4];
        #pragma unroll
        for (int ks = 0; ks < 4; ks++)
            ldmx4(aQ[ks][0], aQ[ks][1], aQ[ks][2], aQ[ks][3],
                  qsb + 2 * (q_lane + ks * 16));

        float O[8][4];
        #pragma unroll
        for (int j = 0; j < 8; j++)
            #pragma unroll
            for (int i = 0; i < 4; i++) O[j][i] = 0.0f;
        float l_g = 0.0f, l_g8 = 0.0f;

        for (int jt = 0; jt < njt; jt++) {
            __syncthreads();
            // ---- Stage K, VH, VL (int4 copies) ----
            {
                int r = tid >> 2, c0 = (tid & 3) * 16;
                const __nv_bfloat16* kb = g_kh + ((size_t)b * T_ + jt * 64 + r) * HD + c0;
                *(int4*)&KS[r * LDW + c0]     = *(const int4*)kb;
                *(int4*)&KS[r * LDW + c0 + 8] = *(const int4*)(kb + 8);
                const __nv_bfloat16* vh = g_vth + ((size_t)b * HD + r) * T_ + jt * 64 + c0;
                *(int4*)&VH[r * LDW + c0]     = *(const int4*)vh;
                *(int4*)&VH[r * LDW + c0 + 8] = *(const int4*)(vh + 8);
                const __nv_bfloat16* vl = g_vtl + ((size_t)b * HD + r) * T_ + jt * 64 + c0;
                *(int4*)&VL[r * LDW + c0]     = *(const int4*)vl;
                *(int4*)&VL[r * LDW + c0 + 8] = *(const int4*)(vl + 8);
            }
            __syncthreads();

            // ---- S = Q K^T over this warp's 32-key half ----
            float S[4][4];
            #pragma unroll
            for (int j = 0; j < 4; j++)
                #pragma unroll
                for (int i = 0; i < 4; i++) S[j][i] = 0.0f;
            #pragma unroll
            for (int ks = 0; ks < 4; ks++) {
                #pragma unroll
                for (int j0 = 0; j0 < 4; j0 += 2) {
                    uint32_t b0, b1, b2, b3;
                    ldmx4(b0, b1, b2, b3,
                          ksb + 2 * (qk_lane + (uint32_t)(j0 * 8 * LDW + ks * 16)));
                    mma16816(S[j0], aQ[ks], b0, b1);
                    mma16816(S[j0 + 1], aQ[ks], b2, b3);
                }
            }

            // ---- softmax (bounded logits, no max subtraction) ----
            const int kb0 = jt * 64 + kh * 32;
            const bool dm = (kb0 + 31) > qrow0;
            #pragma unroll
            for (int j = 0; j < 4; j++) {
                int k0 = kb0 + 8 * j + 2 * t;
                float p0 = __expf(S[j][0] * scale);
                float p1 = __expf(S[j][1] * scale);
                float p2 = __expf(S[j][2] * scale);
                float p3 = __expf(S[j][3] * scale);
                if (dm) {
                    if (k0 > qrow0)     p0 = 0.0f;
                    if (k0 + 1 > qrow0) p1 = 0.0f;
                    if (k0 > qrow8)     p2 = 0.0f;
                    if (k0 + 1 > qrow8) p3 = 0.0f;
                }
                S[j][0] = p0; S[j][1] = p1; S[j][2] = p2; S[j][3] = p3;
                l_g  += p0 + p1;
                l_g8 += p2 + p3;
            }

            // ---- pack P hi/lo a-fragments ----
            uint32_t aH[2][4], aL[2][4];
            #pragma unroll
            for (int kp = 0; kp < 2; kp++)
                #pragma unroll
                for (int hf = 0; hf < 2; hf++) {
                    float* sp = S[2 * kp + hf];
                    #pragma unroll
                    for (int rr = 0; rr < 2; rr++) {
                        float p0 = sp[2 * rr], p1 = sp[2 * rr + 1];
                        __nv_bfloat16 h0 = __float2bfloat16(p0);
                        __nv_bfloat16 h1 = __float2bfloat16(p1);
                        __nv_bfloat162 hh = __halves2bfloat162(h0, h1);
                        aH[kp][hf * 2 + rr] = *(uint32_t*)&hh;
                        aL[kp][hf * 2 + rr] = pk_bf16(
                            p0 - __bfloat162float(h0), p1 - __bfloat162float(h1));
                    }
                }

            // ---- O += Phi Vhi + Plo Vhi + Phi Vlo ----
            #pragma unroll
            for (int ks = 0; ks < 2; ks++) {
                #pragma unroll
                for (int j0 = 0; j0 < 8; j0 += 2) {
                    uint32_t off = 2 * (pv_lane + (uint32_t)(j0 * 8 * LDW + ks * 16));
                    uint32_t h0, h1, h2, h3, l0, l1, l2, l3;
                    ldmx4(h0, h1, h2, h3, vhb + off);
                    ldmx4(l0, l1, l2, l3, vlb + off);
                    mma16816(O[j0], aH[ks], h0, h1);
                    mma16816(O[j0], aL[ks], h0, h1);
                    mma16816(O[j0], aH[ks], l0, l1);
                    mma16816(O[j0 + 1], aH[ks], h2, h3);
                    mma16816(O[j0 + 1], aL[ks], h2, h3);
                    mma16816(O[j0 + 1], aH[ks], l2, l3);
                }
            }
        }

        // ---- reduce l across quad ----
        l_g  += __shfl_xor_sync(0xffffffffu, l_g, 1);
        l_g  += __shfl_xor_sync(0xffffffffu, l_g, 2);
        l_g8 += __shfl_xor_sync(0xffffffffu, l_g8, 1);
        l_g8 += __shfl_xor_sync(0xffffffffu, l_g8, 2);

        __syncthreads();

        if (kh == 1) {
            #pragma unroll
            for (int j = 0; j < 8; j++) {
                int col = 8 * j + 2 * t;
                *(float2*)&Ored[(m0 + g) * ORED_LD + col] = make_float2(O[j][0], O[j][1]);
                *(float2*)&Ored[(m0 + g + 8) * ORED_LD + col] = make_float2(O[j][2], O[j][3]);
            }
            if (t == 0) { lred[m0 + g] = l_g; lred[m0 + g + 8] = l_g8; }
        }
        __syncthreads();

        if (kh == 0) {
            const float il0 = 1.0f / (l_g + lred[m0 + g]);
            const float il1 = 1.0f / (l_g8 + lred[m0 + g + 8]);
            float* ob = out + ((size_t)b * T_ + (size_t)it * 64 + m0) * HD;
            #pragma unroll
            for (int j = 0; j < 8; j++) {
                int col = 8 * j + 2 * t;
                float2 p0 = *(float2*)&Ored[(m0 + g) * ORED_LD + col];
                float2 p1 = *(float2*)&Ored[(m0 + g + 8) * ORED_LD + col];
                *(float2*)&ob[g * HD + col] =
                    make_float2((O[j][0] + p0.x) * il0, (O[j][1] + p0.y) * il0);
                *(float2*)&ob[(g + 8) * HD + col] =
                    make_float2((O[j][2] + p1.x) * il1, (O[j][3] + p1.y) * il1);
            }
        }
        __syncthreads();
    }
}

// ===========================================================================
extern "C" void kernel_launch(void* const* d_in, const int* in_sizes, int n_in,
                              void* d_out, int out_size)
{
    const float* x  = (const float*)d_in[0];
    const float* Wq = (const float*)d_in[1];
    const float* Wk = (const float*)d_in[2];
    const float* Wv = (const float*)d_in[3];
    float* out = (float*)d_out;

    prep_w<<<dim3(16, 3), 256>>>(Wq, Wk, Wv);
    qkv_tc<<<(B_ * T_) / 128, 256>>>(x);
    vt_kernel<<<dim3(T_ / 64, B_), 256>>>();
    attn_mma<<<dim3(32, B_), 256>>>(out);
}

// round 11
// speedup vs baseline: 2.0398x; 1.3764x over previous
#include <cuda_runtime.h>
#include <cuda_bf16.h>
#include <stdint.h>
#include <math.h>

#define B_ 4
#define T_ 4096
#define C_ 1024
#define HD 64

// scratch (no cudaMalloc allowed)
__device__ __nv_bfloat16 g_qh[B_ * T_ * HD];        // Q bf16 [b*t][h]
__device__ __nv_bfloat16 g_kh[B_ * T_ * HD];        // K bf16 [b*t][h]
__device__ float         g_v [B_ * T_ * HD];        // V fp32 [b*t][h]
__device__ __nv_bfloat16 g_vth[B_ * HD * T_];       // V^T hi bf16 [b][h][t]
__device__ __nv_bfloat16 g_vtl[B_ * HD * T_];       // V^T lo
__device__ __nv_bfloat16 g_wth[3 * HD * C_];        // W^T hi bf16 [m][n][k]
__device__ __nv_bfloat16 g_wvl[HD * C_];            // Wv^T lo

// ---------------------------------------------------------------------------
// helpers
// ---------------------------------------------------------------------------
__device__ __forceinline__ uint32_t smem_u32(const void* p) {
    uint32_t a;
    asm("{ .reg .u64 t; cvta.to.shared.u64 t, %1; cvt.u32.u64 %0, t; }"
        : "=r"(a) : "l"(p));
    return a;
}
__device__ __forceinline__ void mma16816(float* c, const uint32_t* a,
                                         uint32_t b0, uint32_t b1) {
    asm volatile(
        "mma.sync.aligned.m16n8k16.row.col.f32.bf16.bf16.f32 "
        "{%0,%1,%2,%3}, {%4,%5,%6,%7}, {%8,%9}, {%0,%1,%2,%3};"
        : "+f"(c[0]), "+f"(c[1]), "+f"(c[2]), "+f"(c[3])
        : "r"(a[0]), "r"(a[1]), "r"(a[2]), "r"(a[3]), "r"(b0), "r"(b1));
}
__device__ __forceinline__ void ldmx4(uint32_t& r0, uint32_t& r1,
                                      uint32_t& r2, uint32_t& r3, uint32_t addr) {
    asm volatile("ldmatrix.sync.aligned.m8n8.x4.shared.b16 {%0,%1,%2,%3}, [%4];"
                 : "=r"(r0), "=r"(r1), "=r"(r2), "=r"(r3) : "r"(addr));
}
__device__ __forceinline__ uint32_t pk_bf16(float lo, float hi) {
    __nv_bfloat162 h = __floats2bfloat162_rn(lo, hi);
    return *(uint32_t*)&h;
}
__device__ __forceinline__ void cpa16(uint32_t saddr, const void* g) {
    asm volatile("cp.async.cg.shared.global [%0], [%1], 16;"
                 :: "r"(saddr), "l"(g) : "memory");
}
#define CPA_COMMIT() asm volatile("cp.async.commit_group;" ::: "memory")
#define CPA_WAIT0()  asm volatile("cp.async.wait_group 0;" ::: "memory")

// ===========================================================================
// Kernel 0: transpose + bf16-split W -> g_wth [m][n][k], g_wvl (v only)
// ===========================================================================
__global__ __launch_bounds__(256) void prep_w(
    const float* __restrict__ Wq, const float* __restrict__ Wk,
    const float* __restrict__ Wv)
{
    __shared__ float s[64][68];
    const int tid = threadIdx.x;
    const int kc = blockIdx.x;
    const int m = blockIdx.y;
    const float* W = (m == 0) ? Wq : (m == 1) ? Wk : Wv;

    {
        int r = tid >> 2, c0 = (tid & 3) * 16;
        const float* wp = W + ((size_t)(kc * 64) + r) * HD + c0;
        #pragma unroll
        for (int i = 0; i < 4; i++)
            *(float4*)&s[r][c0 + i * 4] = *(const float4*)(wp + i * 4);
    }
    __syncthreads();
    {
        int n = tid >> 2, k0 = (tid & 3) * 16;
        __nv_bfloat16* dh = g_wth + ((size_t)m * HD + n) * C_ + kc * 64 + k0;
        __nv_bfloat16* dl = g_wvl + (size_t)n * C_ + kc * 64 + k0;
        #pragma unroll
        for (int i = 0; i < 8; i++) {
            float f0 = s[k0 + 2 * i][n], f1 = s[k0 + 2 * i + 1][n];
            __nv_bfloat16 h0 = __float2bfloat16(f0);
            __nv_bfloat16 h1 = __float2bfloat16(f1);
            __nv_bfloat162 hh = __halves2bfloat162(h0, h1);
            *(uint32_t*)(dh + 2 * i) = *(uint32_t*)&hh;
            if (m == 2)
                *(uint32_t*)(dl + 2 * i) = pk_bf16(
                    f0 - __bfloat162float(h0), f1 - __bfloat162float(h1));
        }
    }
}

// ===========================================================================
// Kernel 1: QKV projection, bf16 mma.sync, cp.async-pipelined.
// W double-buffered via cp.async; X register-prefetched.
// Dynamic smem: XH,XL [128x40] + WT[2][4][64x40] = 61440 B.
// ===========================================================================
#define XS 40
#define WS 40
#define QW_X  0                      // XH 10240 B, then XL 10240 B
#define QW_W  20480                  // 2 bufs x 4 arrays x 5120 B
#define QW_BYTES 61440

__global__ __launch_bounds__(256) void qkv_tc(const float* __restrict__ x)
{
    extern __shared__ __align__(16) char qsm[];
    __nv_bfloat16* XH = (__nv_bfloat16*)(qsm);
    __nv_bfloat16* XL = (__nv_bfloat16*)(qsm + 10240);
    const uint32_t smb = smem_u32(qsm);

    const int tid = threadIdx.x;
    const int w = tid >> 5;
    const int lane = tid & 31;
    const int g = lane >> 2;
    const int t = tid & 3;
    const int m0 = w * 16;
    const long row0 = (long)blockIdx.x * 128;

    const int lr = lane & 7, lh = (lane >> 3) & 1, lj = lane >> 4;
    const uint32_t a_lane = (uint32_t)((m0 + lh * 8 + lr) * XS + lj * 8);
    const uint32_t b_lane = (uint32_t)((lj * 8 + lr) * WS + lh * 8);
    const uint32_t xhb = smb + QW_X, xlb = smb + QW_X + 10240;

    // staging indices
    const int xr = tid >> 1, xc = (tid & 1) * 16;            // X: 4 float4
    const int wa = tid >> 8;                                  // unused; W below
    (void)wa;

    float aq[8][4], ak[8][4], av[8][4];
    #pragma unroll
    for (int j = 0; j < 8; j++)
        #pragma unroll
        for (int i = 0; i < 4; i++) { aq[j][i] = 0; ak[j][i] = 0; av[j][i] = 0; }

    // ---- prologue: X regs chunk 0, W cp.async chunk 0 -> buf 0 ----
    float4 Xr[4];
    {
        const float* xp = x + (row0 + xr) * C_ + xc;
        #pragma unroll
        for (int i = 0; i < 4; i++) Xr[i] = *(const float4*)(xp + i * 4);
    }
    #pragma unroll
    for (int f4 = 0; f4 < 4; f4++) {
        int f = tid + f4 * 256;
        int arr = f >> 8, rw = (f >> 2) & 63, sg = f & 3;
        const __nv_bfloat16* src =
            (arr < 3) ? g_wth + ((size_t)arr * HD + rw) * C_ + sg * 8
                      : g_wvl + (size_t)rw * C_ + sg * 8;
        cpa16(smb + QW_W + (uint32_t)(arr * 5120 + (rw * WS + sg * 8) * 2), src);
    }
    CPA_COMMIT();

    for (int kc = 0; kc < 32; kc++) {
        const int cur = kc & 1;
        CPA_WAIT0();
        __syncthreads();          // prev MMAs' X/W reads done; W buf cur ready

        // convert-store X regs -> smem
        #pragma unroll
        for (int i = 0; i < 4; i++) {
            float4 v = Xr[i];
            __nv_bfloat16 h0 = __float2bfloat16(v.x);
            __nv_bfloat16 h1 = __float2bfloat16(v.y);
            __nv_bfloat16 h2 = __float2bfloat16(v.z);
            __nv_bfloat16 h3 = __float2bfloat16(v.w);
            __nv_bfloat162 a01 = __halves2bfloat162(h0, h1);
            __nv_bfloat162 a23 = __halves2bfloat162(h2, h3);
            *(uint32_t*)&XH[xr * XS + xc + i * 4]     = *(uint32_t*)&a01;
            *(uint32_t*)&XH[xr * XS + xc + i * 4 + 2] = *(uint32_t*)&a23;
            *(uint32_t*)&XL[xr * XS + xc + i * 4] = pk_bf16(
                v.x - __bfloat162float(h0), v.y - __bfloat162float(h1));
            *(uint32_t*)&XL[xr * XS + xc + i * 4 + 2] = pk_bf16(
                v.z - __bfloat162float(h2), v.w - __bfloat162float(h3));
        }
        // prefetch next chunk: X -> regs, W -> other buffer (overlaps MMAs)
        if (kc < 31) {
            const int k0 = (kc + 1) * 32;
            const float* xp = x + (row0 + xr) * C_ + k0 + xc;
            #pragma unroll
            for (int i = 0; i < 4; i++) Xr[i] = *(const float4*)(xp + i * 4);
            #pragma unroll
            for (int f4 = 0; f4 < 4; f4++) {
                int f = tid + f4 * 256;
                int arr = f >> 8, rw = (f >> 2) & 63, sg = f & 3;
                const __nv_bfloat16* src =
                    (arr < 3) ? g_wth + ((size_t)arr * HD + rw) * C_ + k0 + sg * 8
                              : g_wvl + (size_t)rw * C_ + k0 + sg * 8;
                cpa16(smb + QW_W + (uint32_t)((1 - cur) * 20480 + arr * 5120 +
                                              (rw * WS + sg * 8) * 2), src);
            }
            CPA_COMMIT();
        }
        __syncthreads();          // X smem written

        const uint32_t wq  = smb + QW_W + cur * 20480;
        const uint32_t wk  = wq + 5120;
        const uint32_t wvh = wq + 10240;
        const uint32_t wvl = wq + 15360;

        uint32_t aH[2][4], aL[2][4];
        #pragma unroll
        for (int ks = 0; ks < 2; ks++) {
            ldmx4(aH[ks][0], aH[ks][1], aH[ks][2], aH[ks][3],
                  xhb + 2 * (a_lane + ks * 16));
            ldmx4(aL[ks][0], aL[ks][1], aL[ks][2], aL[ks][3],
                  xlb + 2 * (a_lane + ks * 16));
        }
        #pragma unroll
        for (int ks = 0; ks < 2; ks++) {
            #pragma unroll
            for (int j0 = 0; j0 < 8; j0 += 2) {
                uint32_t off = 2 * (b_lane + (uint32_t)(j0 * 8 * WS + ks * 16));
                uint32_t b0, b1, b2, b3;
                ldmx4(b0, b1, b2, b3, wq + off);
                mma16816(aq[j0], aH[ks], b0, b1);
                mma16816(aq[j0 + 1], aH[ks], b2, b3);
                ldmx4(b0, b1, b2, b3, wk + off);
                mma16816(ak[j0], aH[ks], b0, b1);
                mma16816(ak[j0 + 1], aH[ks], b2, b3);
                ldmx4(b0, b1, b2, b3, wvh + off);
                mma16816(av[j0], aH[ks], b0, b1);
                mma16816(av[j0], aL[ks], b0, b1);
                mma16816(av[j0 + 1], aH[ks], b2, b3);
                mma16816(av[j0 + 1], aL[ks], b2, b3);
                ldmx4(b0, b1, b2, b3, wvl + off);
                mma16816(av[j0], aH[ks], b0, b1);
                mma16816(av[j0 + 1], aH[ks], b2, b3);
            }
        }
    }

    // epilogue: q,k -> bf16; v -> fp32
    #pragma unroll
    for (int j = 0; j < 8; j++) {
        int col = 8 * j + 2 * t;
        size_t r0 = (size_t)(row0 + m0 + g) * HD + col;
        size_t r8 = (size_t)(row0 + m0 + g + 8) * HD + col;
        *(uint32_t*)&g_qh[r0] = pk_bf16(aq[j][0], aq[j][1]);
        *(uint32_t*)&g_qh[r8] = pk_bf16(aq[j][2], aq[j][3]);
        *(uint32_t*)&g_kh[r0] = pk_bf16(ak[j][0], ak[j][1]);
        *(uint32_t*)&g_kh[r8] = pk_bf16(ak[j][2], ak[j][3]);
        *(float2*)&g_v[r0] = make_float2(av[j][0], av[j][1]);
        *(float2*)&g_v[r8] = make_float2(av[j][2], av[j][3]);
    }
}

// ===========================================================================
// Kernel 1b: transpose + hi/lo split V -> g_vth/g_vtl [b][h][t]
// ===========================================================================
__global__ __launch_bounds__(256) void vt_kernel()
{
    __shared__ float s[64][68];
    const int tid = threadIdx.x;
    const long t0 = (long)blockIdx.x * 64;
    const int b = blockIdx.y;

    {
        int r = tid >> 2, c0 = (tid & 3) * 16;
        const float* vb = g_v + ((size_t)b * T_ + t0 + r) * HD + c0;
        #pragma unroll
        for (int i = 0; i < 4; i++)
            *(float4*)&s[r][c0 + i * 4] = *(const float4*)(vb + i * 4);
    }
    __syncthreads();
    {
        int h = tid >> 2, ts = (tid & 3) * 16;
        __nv_bfloat16* dh = g_vth + ((size_t)b * HD + h) * T_ + t0 + ts;
        __nv_bfloat16* dl = g_vtl + ((size_t)b * HD + h) * T_ + t0 + ts;
        #pragma unroll
        for (int i = 0; i < 8; i++) {
            float f0 = s[ts + 2 * i][h], f1 = s[ts + 2 * i + 1][h];
            __nv_bfloat16 h0 = __float2bfloat16(f0);
            __nv_bfloat16 h1 = __float2bfloat16(f1);
            __nv_bfloat162 hh = __halves2bfloat162(h0, h1);
            *(uint32_t*)(dh + 2 * i) = *(uint32_t*)&hh;
            *(uint32_t*)(dl + 2 * i) = pk_bf16(
                f0 - __bfloat162float(h0), f1 - __bfloat162float(h1));
        }
    }
}

// ===========================================================================
// Kernel 2: bf16 flash attention, cp.async double-buffered K/VH/VL.
// Dynamic smem: QS + 2x(KS,VH,VL) @ 64x72 bf16 = 64512 B.
// ===========================================================================
#define LDW 72
#define ORED_LD 68
#define A_QS 0
#define A_K(i)  (9216 + (i) * 9216)
#define A_VH(i) (27648 + (i) * 9216)
#define A_VL(i) (46080 + (i) * 9216)
#define A_BYTES 64512

__global__ __launch_bounds__(256, 1) void attn_mma(float* __restrict__ out)
{
    extern __shared__ __align__(16) char dsm[];
    const uint32_t smb = smem_u32(dsm);
    __nv_bfloat16* QS = (__nv_bfloat16*)dsm;

    float* Ored = (float*)(dsm + A_K(0));           // overlay, 17664 B
    float* lred = Ored + 64 * ORED_LD;

    const int tid = threadIdx.x;
    const int w = tid >> 5;
    const int lane = tid & 31;
    const int g = lane >> 2;
    const int t = lane & 3;
    const int m0 = (w & 3) * 16;
    const int kh = w >> 2;
    const int p = blockIdx.x;
    const int b = blockIdx.y;
    const float scale = 0.03125f;

    const int sr = tid >> 2, sc = (tid & 3) * 16;   // staging row/col

    const int lr = lane & 7;
    const int lh = (lane >> 3) & 1;
    const int lj = lane >> 4;
    const uint32_t q_lane  = (uint32_t)((m0 + lh * 8 + lr) * LDW + lj * 8);
    const uint32_t qk_lane = (uint32_t)((kh * 32 + lj * 8 + lr) * LDW + lh * 8);
    const uint32_t pv_lane = (uint32_t)((lj * 8 + lr) * LDW + kh * 32 + lh * 8);

    for (int half = 0; half < 2; half++) {
        const int it = (half == 0) ? (63 - p) : p;
        const int njt = it + 1;
        const int qrow0 = it * 64 + m0 + g;
        const int qrow8 = qrow0 + 8;

        // ---- stage Q + prefetch tile 0 (one cp.async group) ----
        {
            const __nv_bfloat16* qb = g_qh + ((size_t)b * T_ + it * 64 + sr) * HD + sc;
            cpa16(smb + A_QS + (uint32_t)((sr * LDW + sc) * 2), qb);
            cpa16(smb + A_QS + (uint32_t)((sr * LDW + sc + 8) * 2), qb + 8);
            const __nv_bfloat16* kb = g_kh + ((size_t)b * T_ + sr) * HD + sc;
            cpa16(smb + A_K(0) + (uint32_t)((sr * LDW + sc) * 2), kb);
            cpa16(smb + A_K(0) + (uint32_t)((sr * LDW + sc + 8) * 2), kb + 8);
            const __nv_bfloat16* vh = g_vth + ((size_t)b * HD + sr) * T_ + sc;
            cpa16(smb + A_VH(0) + (uint32_t)((sr * LDW + sc) * 2), vh);
            cpa16(smb + A_VH(0) + (uint32_t)((sr * LDW + sc + 8) * 2), vh + 8);
            const __nv_bfloat16* vl = g_vtl + ((size_t)b * HD + sr) * T_ + sc;
            cpa16(smb + A_VL(0) + (uint32_t)((sr * LDW + sc) * 2), vl);
            cpa16(smb + A_VL(0) + (uint32_t)((sr * LDW + sc + 8) * 2), vl + 8);
            CPA_COMMIT();
        }
        CPA_WAIT0();
        __syncthreads();

        uint32_t aQ[4][4];
        #pragma unroll
        for (int ks = 0; ks < 4; ks++)
            ldmx4(aQ[ks][0], aQ[ks][1], aQ[ks][2], aQ[ks][3],
                  smb + A_QS + 2 * (q_lane + ks * 16));

        float O[8][4];
        #pragma unroll
        for (int j = 0; j < 8; j++)
            #pragma unroll
            for (int i = 0; i < 4; i++) O[j][i] = 0.0f;
        float l_g = 0.0f, l_g8 = 0.0f;

        for (int jt = 0; jt < njt; jt++) {
            const int cur = jt & 1;
            if (jt > 0) {             // tile jt's cp.async group in flight
                CPA_WAIT0();
                __syncthreads();
            }
            // prefetch tile jt+1 into other buffer (overlaps compute of jt)
            if (jt + 1 < njt) {
                const int nb = 1 - cur;
                const __nv_bfloat16* kb =
                    g_kh + ((size_t)b * T_ + (jt + 1) * 64 + sr) * HD + sc;
                cpa16(smb + A_K(nb) + (uint32_t)((sr * LDW + sc) * 2), kb);
                cpa16(smb + A_K(nb) + (uint32_t)((sr * LDW + sc + 8) * 2), kb + 8);
                const __nv_bfloat16* vh =
                    g_vth + ((size_t)b * HD + sr) * T_ + (jt + 1) * 64 + sc;
                cpa16(smb + A_VH(nb) + (uint32_t)((sr * LDW + sc) * 2), vh);
                cpa16(smb + A_VH(nb) + (uint32_t)((sr * LDW + sc + 8) * 2), vh + 8);
                const __nv_bfloat16* vl =
                    g_vtl + ((size_t)b * HD + sr) * T_ + (jt + 1) * 64 + sc;
                cpa16(smb + A_VL(nb) + (uint32_t)((sr * LDW + sc) * 2), vl);
                cpa16(smb + A_VL(nb) + (uint32_t)((sr * LDW + sc + 8) * 2), vl + 8);
                CPA_COMMIT();
            }

            const uint32_t ksb = smb + A_K(cur);
            const uint32_t vhb = smb + A_VH(cur);
            const uint32_t vlb = smb + A_VL(cur);

            // ---- S = Q K^T over this warp's 32-key half ----
            float S[4][4];
            #pragma unroll
            for (int j = 0; j < 4; j++)
                #pragma unroll
                for (int i = 0; i < 4; i++) S[j][i] = 0.0f;
            #pragma unroll
            for (int ks = 0; ks < 4; ks++) {
                #pragma unroll
                for (int j0 = 0; j0 < 4; j0 += 2) {
                    uint32_t b0, b1, b2, b3;
                    ldmx4(b0, b1, b2, b3,
                          ksb + 2 * (qk_lane + (uint32_t)(j0 * 8 * LDW + ks * 16)));
                    mma16816(S[j0], aQ[ks], b0, b1);
                    mma16816(S[j0 + 1], aQ[ks], b2, b3);
                }
            }

            // ---- softmax ----
            const int kb0 = jt * 64 + kh * 32;
            const bool dm = (kb0 + 31) > qrow0;
            #pragma unroll
            for (int j = 0; j < 4; j++) {
                int k0 = kb0 + 8 * j + 2 * t;
                float p0 = __expf(S[j][0] * scale);
                float p1 = __expf(S[j][1] * scale);
                float p2 = __expf(S[j][2] * scale);
                float p3 = __expf(S[j][3] * scale);
                if (dm) {
                    if (k0 > qrow0)     p0 = 0.0f;
                    if (k0 + 1 > qrow0) p1 = 0.0f;
                    if (k0 > qrow8)     p2 = 0.0f;
                    if (k0 + 1 > qrow8) p3 = 0.0f;
                }
                S[j][0] = p0; S[j][1] = p1; S[j][2] = p2; S[j][3] = p3;
                l_g  += p0 + p1;
                l_g8 += p2 + p3;
            }

            // ---- pack P hi/lo ----
            uint32_t aH[2][4], aL[2][4];
            #pragma unroll
            for (int kp = 0; kp < 2; kp++)
                #pragma unroll
                for (int hf = 0; hf < 2; hf++) {
                    float* sp = S[2 * kp + hf];
                    #pragma unroll
                    for (int rr = 0; rr < 2; rr++) {
                        float p0 = sp[2 * rr], p1 = sp[2 * rr + 1];
                        __nv_bfloat16 h0 = __float2bfloat16(p0);
                        __nv_bfloat16 h1 = __float2bfloat16(p1);
                        __nv_bfloat162 hh = __halves2bfloat162(h0, h1);
                        aH[kp][hf * 2 + rr] = *(uint32_t*)&hh;
                        aL[kp][hf * 2 + rr] = pk_bf16(
                            p0 - __bfloat162float(h0), p1 - __bfloat162float(h1));
                    }
                }

            // ---- O += Phi Vhi + Plo Vhi + Phi Vlo ----
            #pragma unroll
            for (int ks = 0; ks < 2; ks++) {
                #pragma unroll
                for (int j0 = 0; j0 < 8; j0 += 2) {
                    uint32_t off = 2 * (pv_lane + (uint32_t)(j0 * 8 * LDW + ks * 16));
                    uint32_t h0, h1, h2, h3, l0, l1, l2, l3;
                    ldmx4(h0, h1, h2, h3, vhb + off);
                    ldmx4(l0, l1, l2, l3, vlb + off);
                    mma16816(O[j0], aH[ks], h0, h1);
                    mma16816(O[j0], aL[ks], h0, h1);
                    mma16816(O[j0], aH[ks], l0, l1);
                    mma16816(O[j0 + 1], aH[ks], h2, h3);
                    mma16816(O[j0 + 1], aL[ks], h2, h3);
                    mma16816(O[j0 + 1], aH[ks], l2, l3);
                }
            }
        }

        // ---- reduce l across quad ----
        l_g  += __shfl_xor_sync(0xffffffffu, l_g, 1);
        l_g  += __shfl_xor_sync(0xffffffffu, l_g, 2);
        l_g8 += __shfl_xor_sync(0xffffffffu, l_g8, 1);
        l_g8 += __shfl_xor_sync(0xffffffffu, l_g8, 2);

        __syncthreads();   // all smem reads done before Ored overlay

        if (kh == 1) {
            #pragma unroll
            for (int j = 0; j < 8; j++) {
                int col = 8 * j + 2 * t;
                *(float2*)&Ored[(m0 + g) * ORED_LD + col] = make_float2(O[j][0], O[j][1]);
                *(float2*)&Ored[(m0 + g + 8) * ORED_LD + col] = make_float2(O[j][2], O[j][3]);
            }
            if (t == 0) { lred[m0 + g] = l_g; lred[m0 + g + 8] = l_g8; }
        }
        __syncthreads();

        if (kh == 0) {
            const float il0 = 1.0f / (l_g + lred[m0 + g]);
            const float il1 = 1.0f / (l_g8 + lred[m0 + g + 8]);
            float* ob = out + ((size_t)b * T_ + (size_t)it * 64 + m0) * HD;
            #pragma unroll
            for (int j = 0; j < 8; j++) {
                int col = 8 * j + 2 * t;
                float2 p0 = *(float2*)&Ored[(m0 + g) * ORED_LD + col];
                float2 p1 = *(float2*)&Ored[(m0 + g + 8) * ORED_LD + col];
                *(float2*)&ob[g * HD + col] =
                    make_float2((O[j][0] + p0.x) * il0, (O[j][1] + p0.y) * il0);
                *(float2*)&ob[(g + 8) * HD + col] =
                    make_float2((O[j][2] + p1.x) * il1, (O[j][3] + p1.y) * il1);
            }
        }
        __syncthreads();   // Ored/lred reads done before next half re-stages
    }
}

// ===========================================================================
extern "C" void kernel_launch(void* const* d_in, const int* in_sizes, int n_in,
                              void* d_out, int out_size)
{
    const float* x  = (const float*)d_in[0];
    const float* Wq = (const float*)d_in[1];
    const float* Wk = (const float*)d_in[2];
    const float* Wv = (const float*)d_in[3];
    float* out = (float*)d_out;

    cudaFuncSetAttribute(qkv_tc, cudaFuncAttributeMaxDynamicSharedMemorySize,
                         QW_BYTES);
    cudaFuncSetAttribute(attn_mma, cudaFuncAttributeMaxDynamicSharedMemorySize,
                         A_BYTES);

    prep_w<<<dim3(16, 3), 256>>>(Wq, Wk, Wv);
    qkv_tc<<<(B_ * T_) / 128, 256, QW_BYTES>>>(x);
    vt_kernel<<<dim3(T_ / 64, B_), 256>>>();
    attn_mma<<<dim3(32, B_), 256, A_BYTES>>>(out);
}